// round 12
// baseline (speedup 1.0000x reference)
#include <cuda_runtime.h>
#include <cuda_fp16.h>
#include <cstdint>
#include <math.h>

#define Bq 2
#define Mq 2048
#define Nq 1024
#define Hh 16
#define Dd 64
#define N3 3072
#define MB (Bq*Mq)

// ---------------- scratch (device globals; no cudaMalloc allowed) ----------
__device__ __align__(16) __half g_qkvh[(size_t)MB * N3]; // qkv hi (fp16)
__device__ __align__(16) __half g_qkvl[(size_t)MB * N3]; // qkv lo
__device__ __align__(16) __half g_xh[(size_t)MB * Nq];
__device__ __align__(16) __half g_xl[(size_t)MB * Nq];
__device__ __align__(16) __half g_wah[(size_t)N3 * Nq];  // w_attn^T [n][k]
__device__ __align__(16) __half g_wal[(size_t)N3 * Nq];
__device__ __align__(16) __half g_wph[(size_t)Nq * Nq];  // w_proj^T [n][k]
__device__ __align__(16) __half g_wpl[(size_t)Nq * Nq];
__device__ __align__(16) __half g_ch[(size_t)MB * Nq];   // ctx hi
__device__ __align__(16) __half g_cl[(size_t)MB * Nq];   // ctx lo

// ---------------- PTX plumbing (baseline sm_103, no 'a' features) ----------
__device__ __forceinline__ uint32_t smem_u32(const void* p) {
    uint32_t a;
    asm("{ .reg .u64 t; cvta.to.shared.u64 t, %1; cvt.u32.u64 %0, t; }"
        : "=r"(a) : "l"(p));
    return a;
}
__device__ __forceinline__ void cp16(uint32_t sa, const void* ga) {
    asm volatile("cp.async.cg.shared.global [%0], [%1], 16;"
                 :: "r"(sa), "l"(ga) : "memory");
}
__device__ __forceinline__ void cp_commit() {
    asm volatile("cp.async.commit_group;" ::: "memory");
}
template <int N>
__device__ __forceinline__ void cp_wait() {
    asm volatile("cp.async.wait_group %0;" :: "n"(N) : "memory");
}
__device__ __forceinline__ void ldm4(uint32_t* r, uint32_t addr) {
    asm volatile("ldmatrix.sync.aligned.m8n8.x4.shared.b16 {%0,%1,%2,%3}, [%4];"
                 : "=r"(r[0]), "=r"(r[1]), "=r"(r[2]), "=r"(r[3]) : "r"(addr));
}
__device__ __forceinline__ void ldm4t(uint32_t* r, uint32_t addr) {
    asm volatile("ldmatrix.sync.aligned.m8n8.x4.trans.shared.b16 {%0,%1,%2,%3}, [%4];"
                 : "=r"(r[0]), "=r"(r[1]), "=r"(r[2]), "=r"(r[3]) : "r"(addr));
}
// fp16 mma, fp32 accumulate
__device__ __forceinline__ void mma16816h(float* c, const uint32_t* a,
                                          uint32_t b0, uint32_t b1) {
    asm volatile(
        "mma.sync.aligned.m16n8k16.row.col.f32.f16.f16.f32 "
        "{%0,%1,%2,%3}, {%4,%5,%6,%7}, {%8,%9}, {%0,%1,%2,%3};"
        : "+f"(c[0]), "+f"(c[1]), "+f"(c[2]), "+f"(c[3])
        : "r"(a[0]), "r"(a[1]), "r"(a[2]), "r"(a[3]), "r"(b0), "r"(b1));
}
// pack two f32 -> f16x2 (lo -> low half, hi -> high half)
__device__ __forceinline__ uint32_t packh2(float lo, float hi) {
    __half2 h = __floats2half2_rn(lo, hi);
    return *(uint32_t*)&h;
}
__device__ __forceinline__ float2 unpackh2(uint32_t u) {
    __half2 h = *(__half2*)&u;
    return __half22float2(h);
}
// fast exp on FMA pipe (magic-round exp2, err ~2.4e-6 rel)
__device__ __forceinline__ float fexp(float x) {
    float t = x * 1.4426950408889634f;
    t = fmaxf(t, -125.0f);
    float z = t + 12582912.0f;           // round-to-nearest int
    int iz = __float_as_int(z);
    float fi = z - 12582912.0f;
    float f = t - fi;                    // [-0.5, 0.5]
    float p = 0.00133335581f;
    p = fmaf(p, f, 0.00961812911f);
    p = fmaf(p, f, 0.05550410866f);
    p = fmaf(p, f, 0.24022650700f);
    p = fmaf(p, f, 0.69314718056f);
    p = fmaf(p, f, 1.0f);
    return __int_as_float(__float_as_int(p) + (iz << 23));
}

// ---------------- conversion kernels ----------------------------------------
__global__ void split_kernel(const float* __restrict__ src,
                             __half* __restrict__ hi,
                             __half* __restrict__ lo, int n) {
    int i = blockIdx.x * 256 + threadIdx.x;
    if (i < n) {
        float v = src[i];
        __half h = __float2half_rn(v);
        hi[i] = h;
        lo[i] = __float2half_rn(v - __half2float(h));
    }
}
__global__ void splitT_kernel(const float* __restrict__ W,
                              __half* __restrict__ hT,
                              __half* __restrict__ lT, int K, int N) {
    __shared__ float t[32][33];
    int n0 = blockIdx.x * 32, k0 = blockIdx.y * 32;
    int tx = threadIdx.x, ty = threadIdx.y;
    #pragma unroll
    for (int i = 0; i < 32; i += 8)
        t[ty + i][tx] = W[(size_t)(k0 + ty + i) * N + n0 + tx];
    __syncthreads();
    #pragma unroll
    for (int i = 0; i < 32; i += 8) {
        float v = t[tx][ty + i];
        __half h = __float2half_rn(v);
        size_t o = (size_t)(n0 + ty + i) * K + k0 + tx;
        hT[o] = h;
        lT[o] = __float2half_rn(v - __half2float(h));
    }
}

// ---------------------------------------------------------------------------
// Tensor-core GEMM (fp16x3 emulated fp32, err ~2^-22): C = A@W^T + bias.
// Block 128x128x32, 4 warps (64x64 warp tile), 3-stage cp.async pipeline,
// XOR-swizzled smem, 1 barrier per k-tile, loads issued right after barrier.
// ---------------------------------------------------------------------------
#define MTB 8192                     // bytes per split-matrix tile (128 x 64B)
#define STGB (4 * MTB)               // stage bytes (Ah, Al, Bh, Bl) = 32768
#define GEMM_SMEM (3 * STGB)         // 98304 bytes
#define KTILES (Nq / 32)

// swizzled byte offset for (row r, 16B-chunk c) in a tile with 64B rows
__device__ __forceinline__ uint32_t swz(int r, int c) {
    return (uint32_t)(r * 64 + (((c ^ (r >> 1)) & 3) << 4));
}
// swizzled byte offset for (row r, 16B-chunk c) in a tile with 128B rows
__device__ __forceinline__ uint32_t swz8(int r, int c) {
    return (uint32_t)(r * 128 + (((c ^ r) & 7) << 4));
}

__global__ __launch_bounds__(128, 2)
void gemm_mma(const __half* __restrict__ Ah, const __half* __restrict__ Al,
              const __half* __restrict__ Bh, const __half* __restrict__ Bl,
              const float* __restrict__ bias,
              float* __restrict__ Cf,
              __half* __restrict__ Ch, __half* __restrict__ Cl,
              int N) {
    extern __shared__ __half sm[];
    const int tid = threadIdx.x;
    const int lane = tid & 31, wid = tid >> 5;
    const int wm = wid & 1, wn = wid >> 1;           // warp tile: 64 x 64
    const int bm0 = blockIdx.y * 128, bn0 = blockIdx.x * 128;
    const uint32_t sbase = smem_u32(sm);

    const __half* srcs[4] = {
        Ah + (size_t)bm0 * Nq, Al + (size_t)bm0 * Nq,
        Bh + (size_t)bn0 * Nq, Bl + (size_t)bn0 * Nq };

    const int r0 = tid >> 2;          // 0..31
    const int c0 = tid & 3;           // 16B chunk

    float acc[4][8][4];
    #pragma unroll
    for (int i = 0; i < 4; i++)
        #pragma unroll
        for (int j = 0; j < 8; j++)
            #pragma unroll
            for (int k = 0; k < 4; k++) acc[i][j][k] = 0.0f;

    auto issue = [&](int stg, int kt) {
        uint32_t sb = sbase + (uint32_t)(stg * STGB);
        #pragma unroll
        for (int mi = 0; mi < 4; mi++) {
            #pragma unroll
            for (int it = 0; it < 4; it++) {
                int r = it * 32 + r0;
                cp16(sb + (uint32_t)(mi * MTB) + swz(r, c0),
                     srcs[mi] + (size_t)r * Nq + kt * 32 + c0 * 8);
            }
        }
        cp_commit();
    };

    issue(0, 0);
    issue(1, 1);

    // ldmatrix per-lane bases
    const int aR = wm * 64 + (lane & 15);
    const int chA = lane >> 4;                       // 0/1
    const int bR = wn * 64 + (lane & 7) + ((lane >> 4) << 3);
    const int chB = (lane >> 3) & 1;                 // 0/1

    for (int kt = 0; kt < KTILES; kt++) {
        cp_wait<1>();
        __syncthreads();
        if (kt + 2 < KTILES) issue((kt + 2) % 3, kt + 2);

        const uint32_t stg = sbase + (uint32_t)((kt % 3) * STGB);
        const uint32_t AHb = stg;
        const uint32_t ALb = stg + MTB;
        const uint32_t BHb = stg + 2 * MTB;
        const uint32_t BLb = stg + 3 * MTB;

        #pragma unroll
        for (int ks = 0; ks < 2; ks++) {
            uint32_t ah[4][4], bh[4][4];
            #pragma unroll
            for (int mt = 0; mt < 4; mt++)
                ldm4(ah[mt], AHb + swz(aR + mt * 16, 2 * ks + chA));
            #pragma unroll
            for (int p = 0; p < 4; p++)
                ldm4(bh[p], BHb + swz(bR + p * 16, 2 * ks + chB));
            // Ah . Bh
            #pragma unroll
            for (int mt = 0; mt < 4; mt++)
                #pragma unroll
                for (int nt = 0; nt < 8; nt++)
                    mma16816h(acc[mt][nt], ah[mt], bh[nt >> 1][(nt & 1) * 2],
                              bh[nt >> 1][(nt & 1) * 2 + 1]);
            // Al . Bh
            {
                uint32_t al4[4][4];
                #pragma unroll
                for (int mt = 0; mt < 4; mt++)
                    ldm4(al4[mt], ALb + swz(aR + mt * 16, 2 * ks + chA));
                #pragma unroll
                for (int mt = 0; mt < 4; mt++)
                    #pragma unroll
                    for (int nt = 0; nt < 8; nt++)
                        mma16816h(acc[mt][nt], al4[mt], bh[nt >> 1][(nt & 1) * 2],
                                  bh[nt >> 1][(nt & 1) * 2 + 1]);
            }
            // Ah . Bl
            {
                uint32_t bl4[4][4];
                #pragma unroll
                for (int p = 0; p < 4; p++)
                    ldm4(bl4[p], BLb + swz(bR + p * 16, 2 * ks + chB));
                #pragma unroll
                for (int mt = 0; mt < 4; mt++)
                    #pragma unroll
                    for (int nt = 0; nt < 8; nt++)
                        mma16816h(acc[mt][nt], ah[mt], bl4[nt >> 1][(nt & 1) * 2],
                                  bl4[nt >> 1][(nt & 1) * 2 + 1]);
            }
        }
    }

    const int lr = lane >> 2, lc = lane & 3;
    #pragma unroll
    for (int mt = 0; mt < 4; mt++) {
        int row0 = bm0 + wm * 64 + mt * 16 + lr;
        #pragma unroll
        for (int nt = 0; nt < 8; nt++) {
            int col = bn0 + wn * 64 + nt * 8 + lc * 2;
            float2 bi = *(const float2*)&bias[col];
            float v00 = acc[mt][nt][0] + bi.x, v01 = acc[mt][nt][1] + bi.y;
            float v10 = acc[mt][nt][2] + bi.x, v11 = acc[mt][nt][3] + bi.y;
            if (Cf) {
                float2 o0 = {v00, v01}, o1 = {v10, v11};
                *(float2*)&Cf[(size_t)row0 * N + col] = o0;
                *(float2*)&Cf[(size_t)(row0 + 8) * N + col] = o1;
            } else {
                uint32_t h0 = packh2(v00, v01);
                uint32_t h1 = packh2(v10, v11);
                float2 f0 = unpackh2(h0);
                float2 f1 = unpackh2(h1);
                *(uint32_t*)&Ch[(size_t)row0 * N + col] = h0;
                *(uint32_t*)&Ch[(size_t)(row0 + 8) * N + col] = h1;
                *(uint32_t*)&Cl[(size_t)row0 * N + col] = packh2(v00 - f0.x, v01 - f0.y);
                *(uint32_t*)&Cl[(size_t)(row0 + 8) * N + col] = packh2(v10 - f1.x, v11 - f1.y);
            }
        }
    }
}

// ---------------------------------------------------------------------------
// Tensor-core causal flash attention (fp16 splits).
// QK: 3 products (err ~2^-22). PV: P single fp16 x V hi/lo (2 products).
// CTA: 128 q-rows x d=64, 8 warps x 16 rows. 64-key tiles, 3-stage pipeline.
// ---------------------------------------------------------------------------
#define AQ 128
#define AKT 64
#define STG_A 32768                      // Kh,Kl,Vh,Vl @ 8KB each
#define ATT_SMEM (3 * STG_A)             // 98304 bytes -> 2 CTAs/SM

__global__ __launch_bounds__(256)
void attn_mma() {
    extern __shared__ __half sm[];
    const int tid = threadIdx.x, lane = tid & 31, wid = tid >> 5;
    const int bh = blockIdx.y, b = bh >> 4, h = bh & 15;
    const int qt = gridDim.x - 1 - blockIdx.x;   // heavy tiles first
    const int q0 = qt * AQ;
    const uint32_t sbase = smem_u32(sm);
    const size_t rowb = (size_t)b * Mq;

    const uint32_t QhB = sbase + 2 * STG_A;      // Q parks in stage 2
    const uint32_t QlB = QhB + 16384;

    // ---- load Q tile (hi/lo) into stage-2 region ----
    #pragma unroll
    for (int l = tid; l < 2048; l += 256) {
        int arr = l >> 10;                        // 0:h 1:l
        int r = (l >> 3) & 127;
        int c = l & 7;
        const __half* g = (arr ? g_qkvl : g_qkvh) +
            (rowb + q0 + r) * N3 + h * 64 + c * 8;
        cp16((arr ? QlB : QhB) + swz8(r, c), g);
    }
    cp_commit();

    auto load_kv = [&](int stg_i, int j0) {
        uint32_t base = sbase + (uint32_t)(stg_i * STG_A);
        #pragma unroll
        for (int l = tid; l < 2048; l += 256) {
            int arr = l >> 9;                     // 0:Kh 1:Kl 2:Vh 3:Vl
            int r = (l >> 3) & 63;
            int c = l & 7;
            size_t roff = (rowb + j0 + r) * N3 + h * 64 + c * 8;
            const __half* g =
                (arr == 0) ? g_qkvh + roff + Nq :
                (arr == 1) ? g_qkvl + roff + Nq :
                (arr == 2) ? g_qkvh + roff + 2 * Nq :
                             g_qkvl + roff + 2 * Nq;
            cp16(base + (uint32_t)(arr * 8192) + swz8(r, c), g);
        }
        cp_commit();
    };

    const int nkt = (q0 + AQ) / AKT;             // >= 2 always
    load_kv(0, 0);
    load_kv(1, AKT);

    // ---- Q fragments into registers (once); stage 2 is then free for KV ----
    cp_wait<2>();                                // retires the Q group
    __syncthreads();                             // publish all threads' Q copies
    uint32_t qhf[4][4], qlf[4][4];
    {
        int r = wid * 16 + (lane & 15);
        int chq = lane >> 4;
        #pragma unroll
        for (int ks = 0; ks < 4; ks++) {
            ldm4(qhf[ks], QhB + swz8(r, 2 * ks + chq));
            ldm4(qlf[ks], QlB + swz8(r, 2 * ks + chq));
        }
    }

    float m0 = -1e30f, m1 = -1e30f, l0 = 0.0f, l1 = 0.0f;
    float O[8][4];
    #pragma unroll
    for (int f = 0; f < 8; f++)
        #pragma unroll
        for (int c = 0; c < 4; c++) O[f][c] = 0.0f;

    const float scale = 0.125f;
    const int rbase0 = q0 + wid * 16 + (lane >> 2);
    const int kR = (lane & 7) + ((lane >> 4) << 3);
    const int chK = (lane >> 3) & 1;
    const int vR = lane & 15;
    const int chV = lane >> 4;

    for (int kt = 0; kt < nkt; kt++) {
        const int j0 = kt * AKT;
        if (kt + 1 < nkt) cp_wait<1>();
        else              cp_wait<0>();
        __syncthreads();                          // single barrier per tile
        if (kt + 2 < nkt) load_kv((kt + 2) % 3, (kt + 2) * AKT);

        const uint32_t stg = sbase + (uint32_t)((kt % 3) * STG_A);
        const uint32_t sKh = stg;
        const uint32_t sVh = stg + 16384;

        // ---- scores = Q K^T (3 split products) ----
        float s[8][4];
        #pragma unroll
        for (int f = 0; f < 8; f++)
            #pragma unroll
            for (int c = 0; c < 4; c++) s[f][c] = 0.0f;

        #pragma unroll
        for (int ks = 0; ks < 4; ks++) {
            #pragma unroll
            for (int p = 0; p < 4; p++) {
                uint32_t addr = sKh + swz8(p * 16 + kR, 2 * ks + chK);
                uint32_t kh4[4], kl4[4];
                ldm4(kh4, addr);
                ldm4(kl4, addr + 8192);
                mma16816h(s[2 * p],     qhf[ks], kh4[0], kh4[1]);
                mma16816h(s[2 * p + 1], qhf[ks], kh4[2], kh4[3]);
                mma16816h(s[2 * p],     qhf[ks], kl4[0], kl4[1]);
                mma16816h(s[2 * p + 1], qhf[ks], kl4[2], kl4[3]);
                mma16816h(s[2 * p],     qlf[ks], kh4[0], kh4[1]);
                mma16816h(s[2 * p + 1], qlf[ks], kh4[2], kh4[3]);
            }
        }

        // ---- scale + causal mask (diagonal tiles only) ----
        if (j0 + AKT - 1 > q0) {
            #pragma unroll
            for (int f = 0; f < 8; f++) {
                int k0c = j0 + f * 8 + (lane & 3) * 2;
                #pragma unroll
                for (int c = 0; c < 4; c++) {
                    int key = k0c + (c & 1);
                    int row = rbase0 + ((c >> 1) * 8);
                    s[f][c] = (key > row) ? -1e30f : s[f][c] * scale;
                }
            }
        } else {
            #pragma unroll
            for (int f = 0; f < 8; f++)
                #pragma unroll
                for (int c = 0; c < 4; c++) s[f][c] *= scale;
        }

        // ---- online softmax ----
        float bm0 = -1e30f, bm1 = -1e30f;
        #pragma unroll
        for (int f = 0; f < 8; f++) {
            bm0 = fmaxf(bm0, fmaxf(s[f][0], s[f][1]));
            bm1 = fmaxf(bm1, fmaxf(s[f][2], s[f][3]));
        }
        bm0 = fmaxf(bm0, __shfl_xor_sync(0xffffffff, bm0, 1));
        bm0 = fmaxf(bm0, __shfl_xor_sync(0xffffffff, bm0, 2));
        bm1 = fmaxf(bm1, __shfl_xor_sync(0xffffffff, bm1, 1));
        bm1 = fmaxf(bm1, __shfl_xor_sync(0xffffffff, bm1, 2));
        float mn0 = fmaxf(m0, bm0), mn1 = fmaxf(m1, bm1);
        float corr0 = fexp(m0 - mn0), corr1 = fexp(m1 - mn1);
        m0 = mn0; m1 = mn1;

        float es0 = 0.0f, es1 = 0.0f;
        #pragma unroll
        for (int f = 0; f < 8; f++) {
            s[f][0] = fexp(s[f][0] - m0);
            s[f][1] = fexp(s[f][1] - m0);
            s[f][2] = fexp(s[f][2] - m1);
            s[f][3] = fexp(s[f][3] - m1);
            es0 += s[f][0] + s[f][1];
            es1 += s[f][2] + s[f][3];
        }
        es0 += __shfl_xor_sync(0xffffffff, es0, 1);
        es0 += __shfl_xor_sync(0xffffffff, es0, 2);
        es1 += __shfl_xor_sync(0xffffffff, es1, 1);
        es1 += __shfl_xor_sync(0xffffffff, es1, 2);
        l0 = l0 * corr0 + es0;
        l1 = l1 * corr1 + es1;

        #pragma unroll
        for (int f = 0; f < 8; f++) {
            O[f][0] *= corr0; O[f][1] *= corr0;
            O[f][2] *= corr1; O[f][3] *= corr1;
        }

        // ---- P @ V (P single fp16, V hi/lo: 2 products) ----
        #pragma unroll
        for (int ks2 = 0; ks2 < 4; ks2++) {
            uint32_t aH[4];
            #pragma unroll
            for (int q = 0; q < 2; q++) {
                aH[2 * q + 0] = packh2(s[2 * ks2 + q][0], s[2 * ks2 + q][1]);
                aH[2 * q + 1] = packh2(s[2 * ks2 + q][2], s[2 * ks2 + q][3]);
            }
            #pragma unroll
            for (int p2i = 0; p2i < 4; p2i++) {
                uint32_t addr = sVh + swz8(ks2 * 16 + vR, 2 * p2i + chV);
                uint32_t vh4[4], vl4[4];
                ldm4t(vh4, addr);
                ldm4t(vl4, addr + 8192);
                mma16816h(O[2 * p2i],     aH, vh4[0], vh4[1]);
                mma16816h(O[2 * p2i + 1], aH, vh4[2], vh4[3]);
                mma16816h(O[2 * p2i],     aH, vl4[0], vl4[1]);
                mma16816h(O[2 * p2i + 1], aH, vl4[2], vl4[3]);
            }
        }
    }

    // ---- epilogue: normalize, write ctx fp16 hi/lo ----
    float inv0 = 1.0f / l0, inv1 = 1.0f / l1;
    size_t base0 = (rowb + rbase0) * Nq + h * 64;
    size_t base1 = (rowb + rbase0 + 8) * Nq + h * 64;
    #pragma unroll
    for (int f = 0; f < 8; f++) {
        int col = f * 8 + (lane & 3) * 2;
        float v00 = O[f][0] * inv0, v01 = O[f][1] * inv0;
        float v10 = O[f][2] * inv1, v11 = O[f][3] * inv1;
        uint32_t h0 = packh2(v00, v01);
        uint32_t h1 = packh2(v10, v11);
        float2 f0 = unpackh2(h0);
        float2 f1 = unpackh2(h1);
        *(uint32_t*)&g_ch[base0 + col] = h0;
        *(uint32_t*)&g_cl[base0 + col] = packh2(v00 - f0.x, v01 - f0.y);
        *(uint32_t*)&g_ch[base1 + col] = h1;
        *(uint32_t*)&g_cl[base1 + col] = packh2(v10 - f1.x, v11 - f1.y);
    }
}

// ---------------------------------------------------------------------------
extern "C" void kernel_launch(void* const* d_in, const int* in_sizes, int n_in,
                              void* d_out, int out_size) {
    const float* x      = (const float*)d_in[0];
    const float* w_attn = (const float*)d_in[1];
    const float* w_proj = (const float*)d_in[2];
    const float* b_attn = (const float*)d_in[3];
    const float* b_proj = (const float*)d_in[4];
    float* out = (float*)d_out;

    __half *qh, *ql, *xh, *xl, *wah, *wal, *wph, *wpl, *ch, *cl;
    cudaGetSymbolAddress((void**)&qh, g_qkvh);
    cudaGetSymbolAddress((void**)&ql, g_qkvl);
    cudaGetSymbolAddress((void**)&xh, g_xh);
    cudaGetSymbolAddress((void**)&xl, g_xl);
    cudaGetSymbolAddress((void**)&wah, g_wah);
    cudaGetSymbolAddress((void**)&wal, g_wal);
    cudaGetSymbolAddress((void**)&wph, g_wph);
    cudaGetSymbolAddress((void**)&wpl, g_wpl);
    cudaGetSymbolAddress((void**)&ch, g_ch);
    cudaGetSymbolAddress((void**)&cl, g_cl);

    static bool attr_set = false;
    if (!attr_set) {
        cudaFuncSetAttribute(gemm_mma, cudaFuncAttributeMaxDynamicSharedMemorySize,
                             GEMM_SMEM);
        cudaFuncSetAttribute(attn_mma, cudaFuncAttributeMaxDynamicSharedMemorySize,
                             ATT_SMEM);
        attr_set = true;
    }

    // conversions
    {
        int n = MB * Nq;
        split_kernel<<<(n + 255) / 256, 256>>>(x, xh, xl, n);
    }
    splitT_kernel<<<dim3(N3 / 32, Nq / 32), dim3(32, 8)>>>(w_attn, wah, wal, Nq, N3);
    splitT_kernel<<<dim3(Nq / 32, Nq / 32), dim3(32, 8)>>>(w_proj, wph, wpl, Nq, Nq);

    // QKV projection -> fp16 hi/lo qkv
    gemm_mma<<<dim3(N3 / 128, MB / 128), 128, GEMM_SMEM>>>(
        xh, xl, wah, wal, b_attn, nullptr, qh, ql, N3);

    // causal flash attention -> ctx fp16 hi/lo
    attn_mma<<<dim3(Mq / AQ, Bq * Hh), 256, ATT_SMEM>>>();

    // output projection -> fp32 out
    gemm_mma<<<dim3(Nq / 128, MB / 128), 128, GEMM_SMEM>>>(
        ch, cl, wph, wpl, b_proj, out, nullptr, nullptr, Nq);
}

// round 13
// speedup vs baseline: 1.0673x; 1.0673x over previous
#include <cuda_runtime.h>
#include <cuda_bf16.h>
#include <cuda_fp16.h>
#include <cstdint>
#include <math.h>

#define Bq 2
#define Mq 2048
#define Nq 1024
#define Hh 16
#define Dd 64
#define N3 3072
#define MB (Bq*Mq)

// ---------------- scratch (device globals; no cudaMalloc allowed) ----------
__device__ __align__(16) __half g_qkvh[(size_t)MB * N3];        // qkv hi (fp16)
__device__ __align__(16) __half g_qkvl[(size_t)MB * N3];        // qkv lo (fp16)
__device__ __align__(16) __nv_bfloat16 g_xh[(size_t)MB * Nq];   // x split (bf16)
__device__ __align__(16) __nv_bfloat16 g_xl[(size_t)MB * Nq];
__device__ __align__(16) __nv_bfloat16 g_wah[(size_t)N3 * Nq];  // w_attn^T [n][k]
__device__ __align__(16) __nv_bfloat16 g_wal[(size_t)N3 * Nq];
__device__ __align__(16) __nv_bfloat16 g_wph[(size_t)Nq * Nq];  // w_proj^T [n][k]
__device__ __align__(16) __nv_bfloat16 g_wpl[(size_t)Nq * Nq];
__device__ __align__(16) __nv_bfloat16 g_ch[(size_t)MB * Nq];   // ctx hi (bf16)
__device__ __align__(16) __nv_bfloat16 g_cl[(size_t)MB * Nq];   // ctx lo (bf16)

// ---------------- PTX plumbing (baseline sm_103, no 'a' features) ----------
__device__ __forceinline__ uint32_t smem_u32(const void* p) {
    uint32_t a;
    asm("{ .reg .u64 t; cvta.to.shared.u64 t, %1; cvt.u32.u64 %0, t; }"
        : "=r"(a) : "l"(p));
    return a;
}
__device__ __forceinline__ void cp16(uint32_t sa, const void* ga) {
    asm volatile("cp.async.cg.shared.global [%0], [%1], 16;"
                 :: "r"(sa), "l"(ga) : "memory");
}
__device__ __forceinline__ void cp_commit() {
    asm volatile("cp.async.commit_group;" ::: "memory");
}
template <int N>
__device__ __forceinline__ void cp_wait() {
    asm volatile("cp.async.wait_group %0;" :: "n"(N) : "memory");
}
__device__ __forceinline__ void ldm4(uint32_t* r, uint32_t addr) {
    asm volatile("ldmatrix.sync.aligned.m8n8.x4.shared.b16 {%0,%1,%2,%3}, [%4];"
                 : "=r"(r[0]), "=r"(r[1]), "=r"(r[2]), "=r"(r[3]) : "r"(addr));
}
__device__ __forceinline__ void ldm4t(uint32_t* r, uint32_t addr) {
    asm volatile("ldmatrix.sync.aligned.m8n8.x4.trans.shared.b16 {%0,%1,%2,%3}, [%4];"
                 : "=r"(r[0]), "=r"(r[1]), "=r"(r[2]), "=r"(r[3]) : "r"(addr));
}
// bf16 mma, fp32 accumulate (GEMMs)
__device__ __forceinline__ void mma16816(float* c, const uint32_t* a,
                                         uint32_t b0, uint32_t b1) {
    asm volatile(
        "mma.sync.aligned.m16n8k16.row.col.f32.bf16.bf16.f32 "
        "{%0,%1,%2,%3}, {%4,%5,%6,%7}, {%8,%9}, {%0,%1,%2,%3};"
        : "+f"(c[0]), "+f"(c[1]), "+f"(c[2]), "+f"(c[3])
        : "r"(a[0]), "r"(a[1]), "r"(a[2]), "r"(a[3]), "r"(b0), "r"(b1));
}
// fp16 mma, fp32 accumulate (attention)
__device__ __forceinline__ void mma16816h(float* c, const uint32_t* a,
                                          uint32_t b0, uint32_t b1) {
    asm volatile(
        "mma.sync.aligned.m16n8k16.row.col.f32.f16.f16.f32 "
        "{%0,%1,%2,%3}, {%4,%5,%6,%7}, {%8,%9}, {%0,%1,%2,%3};"
        : "+f"(c[0]), "+f"(c[1]), "+f"(c[2]), "+f"(c[3])
        : "r"(a[0]), "r"(a[1]), "r"(a[2]), "r"(a[3]), "r"(b0), "r"(b1));
}
// packed bf16x2 from two f32 (second operand -> low half)
__device__ __forceinline__ uint32_t cvt2(float hi, float lo) {
    uint32_t r;
    asm("cvt.rn.bf16x2.f32 %0, %1, %2;" : "=r"(r) : "f"(hi), "f"(lo));
    return r;
}
// pack two f32 -> f16x2 (lo -> low half, hi -> high half)
__device__ __forceinline__ uint32_t packh2(float lo, float hi) {
    __half2 h = __floats2half2_rn(lo, hi);
    return *(uint32_t*)&h;
}
__device__ __forceinline__ float2 unpackh2(uint32_t u) {
    __half2 h = *(__half2*)&u;
    return __half22float2(h);
}
// fast exp on FMA pipe (magic-round exp2, err ~2.4e-6 rel)
__device__ __forceinline__ float fexp(float x) {
    float t = x * 1.4426950408889634f;
    t = fmaxf(t, -125.0f);
    float z = t + 12582912.0f;           // round-to-nearest int
    int iz = __float_as_int(z);
    float fi = z - 12582912.0f;
    float f = t - fi;                    // [-0.5, 0.5]
    float p = 0.00133335581f;
    p = fmaf(p, f, 0.00961812911f);
    p = fmaf(p, f, 0.05550410866f);
    p = fmaf(p, f, 0.24022650700f);
    p = fmaf(p, f, 0.69314718056f);
    p = fmaf(p, f, 1.0f);
    return __int_as_float(__float_as_int(p) + (iz << 23));
}

// ---------------- conversion kernels (bf16 splits for GEMM inputs) ----------
__global__ void split_kernel(const float* __restrict__ src,
                             __nv_bfloat16* __restrict__ hi,
                             __nv_bfloat16* __restrict__ lo, int n) {
    int i = blockIdx.x * 256 + threadIdx.x;
    if (i < n) {
        float v = src[i];
        __nv_bfloat16 h = __float2bfloat16(v);
        hi[i] = h;
        lo[i] = __float2bfloat16(v - __bfloat162float(h));
    }
}
__global__ void splitT_kernel(const float* __restrict__ W,
                              __nv_bfloat16* __restrict__ hT,
                              __nv_bfloat16* __restrict__ lT, int K, int N) {
    __shared__ float t[32][33];
    int n0 = blockIdx.x * 32, k0 = blockIdx.y * 32;
    int tx = threadIdx.x, ty = threadIdx.y;
    #pragma unroll
    for (int i = 0; i < 32; i += 8)
        t[ty + i][tx] = W[(size_t)(k0 + ty + i) * N + n0 + tx];
    __syncthreads();
    #pragma unroll
    for (int i = 0; i < 32; i += 8) {
        float v = t[tx][ty + i];
        __nv_bfloat16 h = __float2bfloat16(v);
        size_t o = (size_t)(n0 + ty + i) * K + k0 + tx;
        hT[o] = h;
        lT[o] = __float2bfloat16(v - __bfloat162float(h));
    }
}

// ---------------------------------------------------------------------------
// Tensor-core GEMM (bf16x3 emulated fp32): C = A@W^T + bias.   [R11-proven]
// Block 128x128x32, 4 warps (64x64 warp tile), 3-stage cp.async pipeline,
// XOR-swizzled smem, 1 barrier per k-tile, issue at loop TAIL.
// Epilogue: fp32 out (Cf) OR fp16 hi/lo split out (Ch/Cl, feeds attention).
// ---------------------------------------------------------------------------
#define MTB 8192                     // bytes per split-matrix tile (128 x 64B)
#define STGB (4 * MTB)               // stage bytes (Ah, Al, Bh, Bl) = 32768
#define GEMM_SMEM (3 * STGB)         // 98304 bytes
#define KTILES (Nq / 32)

// swizzled byte offset for (row r, 16B-chunk c) in a tile with 64B rows
__device__ __forceinline__ uint32_t swz(int r, int c) {
    return (uint32_t)(r * 64 + (((c ^ (r >> 1)) & 3) << 4));
}
// swizzled byte offset for (row r, 16B-chunk c) in a tile with 128B rows
__device__ __forceinline__ uint32_t swz8(int r, int c) {
    return (uint32_t)(r * 128 + (((c ^ r) & 7) << 4));
}

__global__ __launch_bounds__(128, 2)
void gemm_mma(const __nv_bfloat16* __restrict__ Ah, const __nv_bfloat16* __restrict__ Al,
              const __nv_bfloat16* __restrict__ Bh, const __nv_bfloat16* __restrict__ Bl,
              const float* __restrict__ bias,
              float* __restrict__ Cf,
              __half* __restrict__ Ch, __half* __restrict__ Cl,
              int N) {
    extern __shared__ __nv_bfloat16 sm[];
    const int tid = threadIdx.x;
    const int lane = tid & 31, wid = tid >> 5;
    const int wm = wid & 1, wn = wid >> 1;           // warp tile: 64 x 64
    const int bm0 = blockIdx.y * 128, bn0 = blockIdx.x * 128;
    const uint32_t sbase = smem_u32(sm);

    const __nv_bfloat16* srcs[4] = {
        Ah + (size_t)bm0 * Nq, Al + (size_t)bm0 * Nq,
        Bh + (size_t)bn0 * Nq, Bl + (size_t)bn0 * Nq };

    const int r0 = tid >> 2;          // 0..31
    const int c0 = tid & 3;           // 16B chunk

    float acc[4][8][4];
    #pragma unroll
    for (int i = 0; i < 4; i++)
        #pragma unroll
        for (int j = 0; j < 8; j++)
            #pragma unroll
            for (int k = 0; k < 4; k++) acc[i][j][k] = 0.0f;

    auto issue = [&](int stg, int kt) {
        uint32_t sb = sbase + (uint32_t)(stg * STGB);
        #pragma unroll
        for (int mi = 0; mi < 4; mi++) {
            #pragma unroll
            for (int it = 0; it < 4; it++) {
                int r = it * 32 + r0;
                cp16(sb + (uint32_t)(mi * MTB) + swz(r, c0),
                     srcs[mi] + (size_t)r * Nq + kt * 32 + c0 * 8);
            }
        }
        cp_commit();
    };

    issue(0, 0);
    issue(1, 1);

    // ldmatrix per-lane bases
    const int aR = wm * 64 + (lane & 15);
    const int chA = lane >> 4;                       // 0/1
    const int bR = wn * 64 + (lane & 7) + ((lane >> 4) << 3);
    const int chB = (lane >> 3) & 1;                 // 0/1

    for (int kt = 0; kt < KTILES; kt++) {
        cp_wait<1>();
        __syncthreads();

        const uint32_t stg = sbase + (uint32_t)((kt % 3) * STGB);
        const uint32_t AHb = stg;
        const uint32_t ALb = stg + MTB;
        const uint32_t BHb = stg + 2 * MTB;
        const uint32_t BLb = stg + 3 * MTB;

        #pragma unroll
        for (int ks = 0; ks < 2; ks++) {
            uint32_t ah[4][4], bh[4][4];
            #pragma unroll
            for (int mt = 0; mt < 4; mt++)
                ldm4(ah[mt], AHb + swz(aR + mt * 16, 2 * ks + chA));
            #pragma unroll
            for (int p = 0; p < 4; p++)
                ldm4(bh[p], BHb + swz(bR + p * 16, 2 * ks + chB));
            // Ah . Bh
            #pragma unroll
            for (int mt = 0; mt < 4; mt++)
                #pragma unroll
                for (int nt = 0; nt < 8; nt++)
                    mma16816(acc[mt][nt], ah[mt], bh[nt >> 1][(nt & 1) * 2],
                             bh[nt >> 1][(nt & 1) * 2 + 1]);
            // Al . Bh
            {
                uint32_t al4[4][4];
                #pragma unroll
                for (int mt = 0; mt < 4; mt++)
                    ldm4(al4[mt], ALb + swz(aR + mt * 16, 2 * ks + chA));
                #pragma unroll
                for (int mt = 0; mt < 4; mt++)
                    #pragma unroll
                    for (int nt = 0; nt < 8; nt++)
                        mma16816(acc[mt][nt], al4[mt], bh[nt >> 1][(nt & 1) * 2],
                                 bh[nt >> 1][(nt & 1) * 2 + 1]);
            }
            // Ah . Bl
            {
                uint32_t bl4[4][4];
                #pragma unroll
                for (int p = 0; p < 4; p++)
                    ldm4(bl4[p], BLb + swz(bR + p * 16, 2 * ks + chB));
                #pragma unroll
                for (int mt = 0; mt < 4; mt++)
                    #pragma unroll
                    for (int nt = 0; nt < 8; nt++)
                        mma16816(acc[mt][nt], ah[mt], bl4[nt >> 1][(nt & 1) * 2],
                                 bl4[nt >> 1][(nt & 1) * 2 + 1]);
            }
        }

        if (kt + 2 < KTILES) issue((kt + 2) % 3, kt + 2);
    }

    const int lr = lane >> 2, lc = lane & 3;
    #pragma unroll
    for (int mt = 0; mt < 4; mt++) {
        int row0 = bm0 + wm * 64 + mt * 16 + lr;
        #pragma unroll
        for (int nt = 0; nt < 8; nt++) {
            int col = bn0 + wn * 64 + nt * 8 + lc * 2;
            float2 bi = *(const float2*)&bias[col];
            float v00 = acc[mt][nt][0] + bi.x, v01 = acc[mt][nt][1] + bi.y;
            float v10 = acc[mt][nt][2] + bi.x, v11 = acc[mt][nt][3] + bi.y;
            if (Cf) {
                float2 o0 = {v00, v01}, o1 = {v10, v11};
                *(float2*)&Cf[(size_t)row0 * N + col] = o0;
                *(float2*)&Cf[(size_t)(row0 + 8) * N + col] = o1;
            } else {
                uint32_t h0 = packh2(v00, v01);
                uint32_t h1 = packh2(v10, v11);
                float2 f0 = unpackh2(h0);
                float2 f1 = unpackh2(h1);
                *(uint32_t*)&Ch[(size_t)row0 * N + col] = h0;
                *(uint32_t*)&Ch[(size_t)(row0 + 8) * N + col] = h1;
                *(uint32_t*)&Cl[(size_t)row0 * N + col] = packh2(v00 - f0.x, v01 - f0.y);
                *(uint32_t*)&Cl[(size_t)(row0 + 8) * N + col] = packh2(v10 - f1.x, v11 - f1.y);
            }
        }
    }
}

// ---------------------------------------------------------------------------
// Tensor-core causal flash attention (fp16).
// QK: 3 products fp16 (err ~2^-22). PV: P single fp16 x V hi/lo (2 products).
// CTA: 128 q-rows x d=64, 8 warps x 16 rows. 64-key tiles, 3-stage pipeline.
// Output ctx written as bf16 hi/lo (feeds bf16 out-proj GEMM).
// ---------------------------------------------------------------------------
#define AQ 128
#define AKT 64
#define STG_A 32768                      // Kh,Kl,Vh,Vl @ 8KB each
#define ATT_SMEM (3 * STG_A)             // 98304 bytes -> 2 CTAs/SM

__global__ __launch_bounds__(256)
void attn_mma() {
    extern __shared__ __half smh[];
    const int tid = threadIdx.x, lane = tid & 31, wid = tid >> 5;
    const int bh = blockIdx.y, b = bh >> 4, h = bh & 15;
    const int qt = gridDim.x - 1 - blockIdx.x;   // heavy tiles first
    const int q0 = qt * AQ;
    const uint32_t sbase = smem_u32(smh);
    const size_t rowb = (size_t)b * Mq;

    const uint32_t QhB = sbase + 2 * STG_A;      // Q parks in stage 2
    const uint32_t QlB = QhB + 16384;

    // ---- load Q tile (hi/lo) into stage-2 region ----
    #pragma unroll
    for (int l = tid; l < 2048; l += 256) {
        int arr = l >> 10;                        // 0:h 1:l
        int r = (l >> 3) & 127;
        int c = l & 7;
        const __half* g = (arr ? g_qkvl : g_qkvh) +
            (rowb + q0 + r) * N3 + h * 64 + c * 8;
        cp16((arr ? QlB : QhB) + swz8(r, c), g);
    }
    cp_commit();

    auto load_kv = [&](int stg_i, int j0) {
        uint32_t base = sbase + (uint32_t)(stg_i * STG_A);
        #pragma unroll
        for (int l = tid; l < 2048; l += 256) {
            int arr = l >> 9;                     // 0:Kh 1:Kl 2:Vh 3:Vl
            int r = (l >> 3) & 63;
            int c = l & 7;
            size_t roff = (rowb + j0 + r) * N3 + h * 64 + c * 8;
            const __half* g =
                (arr == 0) ? g_qkvh + roff + Nq :
                (arr == 1) ? g_qkvl + roff + Nq :
                (arr == 2) ? g_qkvh + roff + 2 * Nq :
                             g_qkvl + roff + 2 * Nq;
            cp16(base + (uint32_t)(arr * 8192) + swz8(r, c), g);
        }
        cp_commit();
    };

    const int nkt = (q0 + AQ) / AKT;             // >= 2 always
    load_kv(0, 0);
    load_kv(1, AKT);

    // ---- Q fragments into registers (once); stage 2 is then free for KV ----
    cp_wait<2>();                                // retires the Q group
    __syncthreads();                             // publish all threads' Q copies
    uint32_t qhf[4][4], qlf[4][4];
    {
        int r = wid * 16 + (lane & 15);
        int chq = lane >> 4;
        #pragma unroll
        for (int ks = 0; ks < 4; ks++) {
            ldm4(qhf[ks], QhB + swz8(r, 2 * ks + chq));
            ldm4(qlf[ks], QlB + swz8(r, 2 * ks + chq));
        }
    }

    float m0 = -1e30f, m1 = -1e30f, l0 = 0.0f, l1 = 0.0f;
    float O[8][4];
    #pragma unroll
    for (int f = 0; f < 8; f++)
        #pragma unroll
        for (int c = 0; c < 4; c++) O[f][c] = 0.0f;

    const float scale = 0.125f;
    const int rbase0 = q0 + wid * 16 + (lane >> 2);
    const int kR = (lane & 7) + ((lane >> 4) << 3);
    const int chK = (lane >> 3) & 1;
    const int vR = lane & 15;
    const int chV = lane >> 4;

    for (int kt = 0; kt < nkt; kt++) {
        const int j0 = kt * AKT;
        if (kt + 1 < nkt) cp_wait<1>();
        else              cp_wait<0>();
        __syncthreads();                          // single barrier per tile
        if (kt + 2 < nkt) load_kv((kt + 2) % 3, (kt + 2) * AKT);

        const uint32_t stg = sbase + (uint32_t)((kt % 3) * STG_A);
        const uint32_t sKh = stg;
        const uint32_t sVh = stg + 16384;

        // ---- scores = Q K^T (3 split products) ----
        float s[8][4];
        #pragma unroll
        for (int f = 0; f < 8; f++)
            #pragma unroll
            for (int c = 0; c < 4; c++) s[f][c] = 0.0f;

        #pragma unroll
        for (int ks = 0; ks < 4; ks++) {
            #pragma unroll
            for (int p = 0; p < 4; p++) {
                uint32_t addr = sKh + swz8(p * 16 + kR, 2 * ks + chK);
                uint32_t kh4[4], kl4[4];
                ldm4(kh4, addr);
                ldm4(kl4, addr + 8192);
                mma16816h(s[2 * p],     qhf[ks], kh4[0], kh4[1]);
                mma16816h(s[2 * p + 1], qhf[ks], kh4[2], kh4[3]);
                mma16816h(s[2 * p],     qhf[ks], kl4[0], kl4[1]);
                mma16816h(s[2 * p + 1], qhf[ks], kl4[2], kl4[3]);
                mma16816h(s[2 * p],     qlf[ks], kh4[0], kh4[1]);
                mma16816h(s[2 * p + 1], qlf[ks], kh4[2], kh4[3]);
            }
        }

        // ---- scale + causal mask (diagonal tiles only) ----
        if (j0 + AKT - 1 > q0) {
            #pragma unroll
            for (int f = 0; f < 8; f++) {
                int k0c = j0 + f * 8 + (lane & 3) * 2;
                #pragma unroll
                for (int c = 0; c < 4; c++) {
                    int key = k0c + (c & 1);
                    int row = rbase0 + ((c >> 1) * 8);
                    s[f][c] = (key > row) ? -1e30f : s[f][c] * scale;
                }
            }
        } else {
            #pragma unroll
            for (int f = 0; f < 8; f++)
                #pragma unroll
                for (int c = 0; c < 4; c++) s[f][c] *= scale;
        }

        // ---- online softmax ----
        float bm0 = -1e30f, bm1 = -1e30f;
        #pragma unroll
        for (int f = 0; f < 8; f++) {
            bm0 = fmaxf(bm0, fmaxf(s[f][0], s[f][1]));
            bm1 = fmaxf(bm1, fmaxf(s[f][2], s[f][3]));
        }
        bm0 = fmaxf(bm0, __shfl_xor_sync(0xffffffff, bm0, 1));
        bm0 = fmaxf(bm0, __shfl_xor_sync(0xffffffff, bm0, 2));
        bm1 = fmaxf(bm1, __shfl_xor_sync(0xffffffff, bm1, 1));
        bm1 = fmaxf(bm1, __shfl_xor_sync(0xffffffff, bm1, 2));
        float mn0 = fmaxf(m0, bm0), mn1 = fmaxf(m1, bm1);
        float corr0 = fexp(m0 - mn0), corr1 = fexp(m1 - mn1);
        m0 = mn0; m1 = mn1;

        float es0 = 0.0f, es1 = 0.0f;
        #pragma unroll
        for (int f = 0; f < 8; f++) {
            s[f][0] = fexp(s[f][0] - m0);
            s[f][1] = fexp(s[f][1] - m0);
            s[f][2] = fexp(s[f][2] - m1);
            s[f][3] = fexp(s[f][3] - m1);
            es0 += s[f][0] + s[f][1];
            es1 += s[f][2] + s[f][3];
        }
        es0 += __shfl_xor_sync(0xffffffff, es0, 1);
        es0 += __shfl_xor_sync(0xffffffff, es0, 2);
        es1 += __shfl_xor_sync(0xffffffff, es1, 1);
        es1 += __shfl_xor_sync(0xffffffff, es1, 2);
        l0 = l0 * corr0 + es0;
        l1 = l1 * corr1 + es1;

        #pragma unroll
        for (int f = 0; f < 8; f++) {
            O[f][0] *= corr0; O[f][1] *= corr0;
            O[f][2] *= corr1; O[f][3] *= corr1;
        }

        // ---- P @ V (P single fp16, V hi/lo: 2 products) ----
        #pragma unroll
        for (int ks2 = 0; ks2 < 4; ks2++) {
            uint32_t aH[4];
            #pragma unroll
            for (int q = 0; q < 2; q++) {
                aH[2 * q + 0] = packh2(s[2 * ks2 + q][0], s[2 * ks2 + q][1]);
                aH[2 * q + 1] = packh2(s[2 * ks2 + q][2], s[2 * ks2 + q][3]);
            }
            #pragma unroll
            for (int p2i = 0; p2i < 4; p2i++) {
                uint32_t addr = sVh + swz8(ks2 * 16 + vR, 2 * p2i + chV);
                uint32_t vh4[4], vl4[4];
                ldm4t(vh4, addr);
                ldm4t(vl4, addr + 8192);
                mma16816h(O[2 * p2i],     aH, vh4[0], vh4[1]);
                mma16816h(O[2 * p2i + 1], aH, vh4[2], vh4[3]);
                mma16816h(O[2 * p2i],     aH, vl4[0], vl4[1]);
                mma16816h(O[2 * p2i + 1], aH, vl4[2], vl4[3]);
            }
        }
    }

    // ---- epilogue: normalize, write ctx bf16 hi/lo ----
    float inv0 = 1.0f / l0, inv1 = 1.0f / l1;
    size_t base0 = (rowb + rbase0) * Nq + h * 64;
    size_t base1 = (rowb + rbase0 + 8) * Nq + h * 64;
    #pragma unroll
    for (int f = 0; f < 8; f++) {
        int col = f * 8 + (lane & 3) * 2;
        float v00 = O[f][0] * inv0, v01 = O[f][1] * inv0;
        float v10 = O[f][2] * inv1, v11 = O[f][3] * inv1;
        uint32_t h0 = cvt2(v01, v00);
        uint32_t h1 = cvt2(v11, v10);
        float r00 = v00 - __int_as_float(h0 << 16);
        float r01 = v01 - __int_as_float(h0 & 0xffff0000u);
        float r10 = v10 - __int_as_float(h1 << 16);
        float r11 = v11 - __int_as_float(h1 & 0xffff0000u);
        *(uint32_t*)&g_ch[base0 + col] = h0;
        *(uint32_t*)&g_cl[base0 + col] = cvt2(r01, r00);
        *(uint32_t*)&g_ch[base1 + col] = h1;
        *(uint32_t*)&g_cl[base1 + col] = cvt2(r11, r10);
    }
}

// ---------------------------------------------------------------------------
extern "C" void kernel_launch(void* const* d_in, const int* in_sizes, int n_in,
                              void* d_out, int out_size) {
    const float* x      = (const float*)d_in[0];
    const float* w_attn = (const float*)d_in[1];
    const float* w_proj = (const float*)d_in[2];
    const float* b_attn = (const float*)d_in[3];
    const float* b_proj = (const float*)d_in[4];
    float* out = (float*)d_out;

    __half *qh, *ql;
    __nv_bfloat16 *xh, *xl, *wah, *wal, *wph, *wpl, *ch, *cl;
    cudaGetSymbolAddress((void**)&qh, g_qkvh);
    cudaGetSymbolAddress((void**)&ql, g_qkvl);
    cudaGetSymbolAddress((void**)&xh, g_xh);
    cudaGetSymbolAddress((void**)&xl, g_xl);
    cudaGetSymbolAddress((void**)&wah, g_wah);
    cudaGetSymbolAddress((void**)&wal, g_wal);
    cudaGetSymbolAddress((void**)&wph, g_wph);
    cudaGetSymbolAddress((void**)&wpl, g_wpl);
    cudaGetSymbolAddress((void**)&ch, g_ch);
    cudaGetSymbolAddress((void**)&cl, g_cl);

    static bool attr_set = false;
    if (!attr_set) {
        cudaFuncSetAttribute(gemm_mma, cudaFuncAttributeMaxDynamicSharedMemorySize,
                             GEMM_SMEM);
        cudaFuncSetAttribute(attn_mma, cudaFuncAttributeMaxDynamicSharedMemorySize,
                             ATT_SMEM);
        attr_set = true;
    }

    // conversions (bf16 splits for the GEMM inputs)
    {
        int n = MB * Nq;
        split_kernel<<<(n + 255) / 256, 256>>>(x, xh, xl, n);
    }
    splitT_kernel<<<dim3(N3 / 32, Nq / 32), dim3(32, 8)>>>(w_attn, wah, wal, Nq, N3);
    splitT_kernel<<<dim3(Nq / 32, Nq / 32), dim3(32, 8)>>>(w_proj, wph, wpl, Nq, Nq);

    // QKV projection (bf16 math) -> fp16 hi/lo qkv
    gemm_mma<<<dim3(N3 / 128, MB / 128), 128, GEMM_SMEM>>>(
        xh, xl, wah, wal, b_attn, nullptr, qh, ql, N3);

    // causal flash attention (fp16) -> ctx bf16 hi/lo
    attn_mma<<<dim3(Mq / AQ, Bq * Hh), 256, ATT_SMEM>>>();

    // output projection (bf16 math) -> fp32 out
    gemm_mma<<<dim3(Nq / 128, MB / 128), 128, GEMM_SMEM>>>(
        ch, cl, wph, wpl, b_proj, out, nullptr, nullptr, Nq);
}

// round 14
// speedup vs baseline: 1.0686x; 1.0013x over previous
#include <cuda_runtime.h>
#include <cuda_bf16.h>
#include <cuda_fp16.h>
#include <cstdint>
#include <math.h>

#define Bq 2
#define Mq 2048
#define Nq 1024
#define Hh 16
#define Dd 64
#define N3 3072
#define MB (Bq*Mq)

// ---------------- scratch (device globals; no cudaMalloc allowed) ----------
__device__ __align__(16) __half g_qkvh[(size_t)MB * N3];        // qkv hi (fp16)
__device__ __align__(16) __half g_qkvl[(size_t)MB * N3];        // qkv lo (fp16)
__device__ __align__(16) __nv_bfloat16 g_xh[(size_t)MB * Nq];   // x split (bf16)
__device__ __align__(16) __nv_bfloat16 g_xl[(size_t)MB * Nq];
__device__ __align__(16) __nv_bfloat16 g_wah[(size_t)N3 * Nq];  // w_attn^T [n][k]
__device__ __align__(16) __nv_bfloat16 g_wal[(size_t)N3 * Nq];
__device__ __align__(16) __nv_bfloat16 g_wph[(size_t)Nq * Nq];  // w_proj^T [n][k]
__device__ __align__(16) __nv_bfloat16 g_wpl[(size_t)Nq * Nq];
__device__ __align__(16) __nv_bfloat16 g_ch[(size_t)MB * Nq];   // ctx hi (bf16)
__device__ __align__(16) __nv_bfloat16 g_cl[(size_t)MB * Nq];   // ctx lo (bf16)

// ---------------- PTX plumbing (baseline sm_103, no 'a' features) ----------
__device__ __forceinline__ uint32_t smem_u32(const void* p) {
    uint32_t a;
    asm("{ .reg .u64 t; cvta.to.shared.u64 t, %1; cvt.u32.u64 %0, t; }"
        : "=r"(a) : "l"(p));
    return a;
}
__device__ __forceinline__ void cp16(uint32_t sa, const void* ga) {
    asm volatile("cp.async.cg.shared.global [%0], [%1], 16;"
                 :: "r"(sa), "l"(ga) : "memory");
}
__device__ __forceinline__ void cp_commit() {
    asm volatile("cp.async.commit_group;" ::: "memory");
}
template <int N>
__device__ __forceinline__ void cp_wait() {
    asm volatile("cp.async.wait_group %0;" :: "n"(N) : "memory");
}
__device__ __forceinline__ void ldm4(uint32_t* r, uint32_t addr) {
    asm volatile("ldmatrix.sync.aligned.m8n8.x4.shared.b16 {%0,%1,%2,%3}, [%4];"
                 : "=r"(r[0]), "=r"(r[1]), "=r"(r[2]), "=r"(r[3]) : "r"(addr));
}
__device__ __forceinline__ void ldm4t(uint32_t* r, uint32_t addr) {
    asm volatile("ldmatrix.sync.aligned.m8n8.x4.trans.shared.b16 {%0,%1,%2,%3}, [%4];"
                 : "=r"(r[0]), "=r"(r[1]), "=r"(r[2]), "=r"(r[3]) : "r"(addr));
}
// bf16 mma, fp32 accumulate (GEMMs)
__device__ __forceinline__ void mma16816(float* c, const uint32_t* a,
                                         uint32_t b0, uint32_t b1) {
    asm volatile(
        "mma.sync.aligned.m16n8k16.row.col.f32.bf16.bf16.f32 "
        "{%0,%1,%2,%3}, {%4,%5,%6,%7}, {%8,%9}, {%0,%1,%2,%3};"
        : "+f"(c[0]), "+f"(c[1]), "+f"(c[2]), "+f"(c[3])
        : "r"(a[0]), "r"(a[1]), "r"(a[2]), "r"(a[3]), "r"(b0), "r"(b1));
}
// fp16 mma, fp32 accumulate (attention)
__device__ __forceinline__ void mma16816h(float* c, const uint32_t* a,
                                          uint32_t b0, uint32_t b1) {
    asm volatile(
        "mma.sync.aligned.m16n8k16.row.col.f32.f16.f16.f32 "
        "{%0,%1,%2,%3}, {%4,%5,%6,%7}, {%8,%9}, {%0,%1,%2,%3};"
        : "+f"(c[0]), "+f"(c[1]), "+f"(c[2]), "+f"(c[3])
        : "r"(a[0]), "r"(a[1]), "r"(a[2]), "r"(a[3]), "r"(b0), "r"(b1));
}
// packed bf16x2 from two f32 (second operand -> low half)
__device__ __forceinline__ uint32_t cvt2(float hi, float lo) {
    uint32_t r;
    asm("cvt.rn.bf16x2.f32 %0, %1, %2;" : "=r"(r) : "f"(hi), "f"(lo));
    return r;
}
// pack two f32 -> f16x2 (lo -> low half, hi -> high half)
__device__ __forceinline__ uint32_t packh2(float lo, float hi) {
    __half2 h = __floats2half2_rn(lo, hi);
    return *(uint32_t*)&h;
}
__device__ __forceinline__ float2 unpackh2(uint32_t u) {
    __half2 h = *(__half2*)&u;
    return __half22float2(h);
}
// fast exp on FMA pipe (magic-round exp2, err ~2.4e-6 rel)
__device__ __forceinline__ float fexp(float x) {
    float t = x * 1.4426950408889634f;
    t = fmaxf(t, -125.0f);
    float z = t + 12582912.0f;           // round-to-nearest int
    int iz = __float_as_int(z);
    float fi = z - 12582912.0f;
    float f = t - fi;                    // [-0.5, 0.5]
    float p = 0.00133335581f;
    p = fmaf(p, f, 0.00961812911f);
    p = fmaf(p, f, 0.05550410866f);
    p = fmaf(p, f, 0.24022650700f);
    p = fmaf(p, f, 0.69314718056f);
    p = fmaf(p, f, 1.0f);
    return __int_as_float(__float_as_int(p) + (iz << 23));
}

// ---------------- conversion kernels (bf16 splits for GEMM inputs) ----------
__global__ void split_kernel(const float* __restrict__ src,
                             __nv_bfloat16* __restrict__ hi,
                             __nv_bfloat16* __restrict__ lo, int n) {
    int i = blockIdx.x * 256 + threadIdx.x;
    if (i < n) {
        float v = src[i];
        __nv_bfloat16 h = __float2bfloat16(v);
        hi[i] = h;
        lo[i] = __float2bfloat16(v - __bfloat162float(h));
    }
}
__global__ void splitT_kernel(const float* __restrict__ W,
                              __nv_bfloat16* __restrict__ hT,
                              __nv_bfloat16* __restrict__ lT, int K, int N) {
    __shared__ float t[32][33];
    int n0 = blockIdx.x * 32, k0 = blockIdx.y * 32;
    int tx = threadIdx.x, ty = threadIdx.y;
    #pragma unroll
    for (int i = 0; i < 32; i += 8)
        t[ty + i][tx] = W[(size_t)(k0 + ty + i) * N + n0 + tx];
    __syncthreads();
    #pragma unroll
    for (int i = 0; i < 32; i += 8) {
        float v = t[tx][ty + i];
        __nv_bfloat16 h = __float2bfloat16(v);
        size_t o = (size_t)(n0 + ty + i) * K + k0 + tx;
        hT[o] = h;
        lT[o] = __float2bfloat16(v - __bfloat162float(h));
    }
}

// ---------------------------------------------------------------------------
// Tensor-core GEMM (bf16x3 emulated fp32): C = A@W^T + bias.   [R11-proven]
// Block 128x128x32, 4 warps (64x64 warp tile), 3-stage cp.async pipeline,
// XOR-swizzled smem, 1 barrier per k-tile, issue at loop TAIL.
// Epilogue: fp32 out (Cf) OR fp16 hi/lo split out (Ch/Cl, feeds attention).
// ---------------------------------------------------------------------------
#define MTB 8192                     // bytes per split-matrix tile (128 x 64B)
#define STGB (4 * MTB)               // stage bytes (Ah, Al, Bh, Bl) = 32768
#define GEMM_SMEM (3 * STGB)         // 98304 bytes
#define KTILES (Nq / 32)

// swizzled byte offset for (row r, 16B-chunk c) in a tile with 64B rows
__device__ __forceinline__ uint32_t swz(int r, int c) {
    return (uint32_t)(r * 64 + (((c ^ (r >> 1)) & 3) << 4));
}
// swizzled byte offset for (row r, 16B-chunk c) in a tile with 128B rows
__device__ __forceinline__ uint32_t swz8(int r, int c) {
    return (uint32_t)(r * 128 + (((c ^ r) & 7) << 4));
}

__global__ __launch_bounds__(128, 2)
void gemm_mma(const __nv_bfloat16* __restrict__ Ah, const __nv_bfloat16* __restrict__ Al,
              const __nv_bfloat16* __restrict__ Bh, const __nv_bfloat16* __restrict__ Bl,
              const float* __restrict__ bias,
              float* __restrict__ Cf,
              __half* __restrict__ Ch, __half* __restrict__ Cl,
              int N) {
    extern __shared__ __nv_bfloat16 sm[];
    const int tid = threadIdx.x;
    const int lane = tid & 31, wid = tid >> 5;
    const int wm = wid & 1, wn = wid >> 1;           // warp tile: 64 x 64
    const int bm0 = blockIdx.y * 128, bn0 = blockIdx.x * 128;
    const uint32_t sbase = smem_u32(sm);

    const __nv_bfloat16* srcs[4] = {
        Ah + (size_t)bm0 * Nq, Al + (size_t)bm0 * Nq,
        Bh + (size_t)bn0 * Nq, Bl + (size_t)bn0 * Nq };

    const int r0 = tid >> 2;          // 0..31
    const int c0 = tid & 3;           // 16B chunk

    float acc[4][8][4];
    #pragma unroll
    for (int i = 0; i < 4; i++)
        #pragma unroll
        for (int j = 0; j < 8; j++)
            #pragma unroll
            for (int k = 0; k < 4; k++) acc[i][j][k] = 0.0f;

    auto issue = [&](int stg, int kt) {
        uint32_t sb = sbase + (uint32_t)(stg * STGB);
        #pragma unroll
        for (int mi = 0; mi < 4; mi++) {
            #pragma unroll
            for (int it = 0; it < 4; it++) {
                int r = it * 32 + r0;
                cp16(sb + (uint32_t)(mi * MTB) + swz(r, c0),
                     srcs[mi] + (size_t)r * Nq + kt * 32 + c0 * 8);
            }
        }
        cp_commit();
    };

    issue(0, 0);
    issue(1, 1);

    // ldmatrix per-lane bases
    const int aR = wm * 64 + (lane & 15);
    const int chA = lane >> 4;                       // 0/1
    const int bR = wn * 64 + (lane & 7) + ((lane >> 4) << 3);
    const int chB = (lane >> 3) & 1;                 // 0/1

    for (int kt = 0; kt < KTILES; kt++) {
        cp_wait<1>();
        __syncthreads();

        const uint32_t stg = sbase + (uint32_t)((kt % 3) * STGB);
        const uint32_t AHb = stg;
        const uint32_t ALb = stg + MTB;
        const uint32_t BHb = stg + 2 * MTB;
        const uint32_t BLb = stg + 3 * MTB;

        #pragma unroll
        for (int ks = 0; ks < 2; ks++) {
            uint32_t ah[4][4], bh[4][4];
            #pragma unroll
            for (int mt = 0; mt < 4; mt++)
                ldm4(ah[mt], AHb + swz(aR + mt * 16, 2 * ks + chA));
            #pragma unroll
            for (int p = 0; p < 4; p++)
                ldm4(bh[p], BHb + swz(bR + p * 16, 2 * ks + chB));
            // Ah . Bh
            #pragma unroll
            for (int mt = 0; mt < 4; mt++)
                #pragma unroll
                for (int nt = 0; nt < 8; nt++)
                    mma16816(acc[mt][nt], ah[mt], bh[nt >> 1][(nt & 1) * 2],
                             bh[nt >> 1][(nt & 1) * 2 + 1]);
            // Al . Bh
            {
                uint32_t al4[4][4];
                #pragma unroll
                for (int mt = 0; mt < 4; mt++)
                    ldm4(al4[mt], ALb + swz(aR + mt * 16, 2 * ks + chA));
                #pragma unroll
                for (int mt = 0; mt < 4; mt++)
                    #pragma unroll
                    for (int nt = 0; nt < 8; nt++)
                        mma16816(acc[mt][nt], al4[mt], bh[nt >> 1][(nt & 1) * 2],
                                 bh[nt >> 1][(nt & 1) * 2 + 1]);
            }
            // Ah . Bl
            {
                uint32_t bl4[4][4];
                #pragma unroll
                for (int p = 0; p < 4; p++)
                    ldm4(bl4[p], BLb + swz(bR + p * 16, 2 * ks + chB));
                #pragma unroll
                for (int mt = 0; mt < 4; mt++)
                    #pragma unroll
                    for (int nt = 0; nt < 8; nt++)
                        mma16816(acc[mt][nt], ah[mt], bl4[nt >> 1][(nt & 1) * 2],
                                 bl4[nt >> 1][(nt & 1) * 2 + 1]);
            }
        }

        if (kt + 2 < KTILES) issue((kt + 2) % 3, kt + 2);
    }

    const int lr = lane >> 2, lc = lane & 3;
    #pragma unroll
    for (int mt = 0; mt < 4; mt++) {
        int row0 = bm0 + wm * 64 + mt * 16 + lr;
        #pragma unroll
        for (int nt = 0; nt < 8; nt++) {
            int col = bn0 + wn * 64 + nt * 8 + lc * 2;
            float2 bi = *(const float2*)&bias[col];
            float v00 = acc[mt][nt][0] + bi.x, v01 = acc[mt][nt][1] + bi.y;
            float v10 = acc[mt][nt][2] + bi.x, v11 = acc[mt][nt][3] + bi.y;
            if (Cf) {
                float2 o0 = {v00, v01}, o1 = {v10, v11};
                *(float2*)&Cf[(size_t)row0 * N + col] = o0;
                *(float2*)&Cf[(size_t)(row0 + 8) * N + col] = o1;
            } else {
                uint32_t h0 = packh2(v00, v01);
                uint32_t h1 = packh2(v10, v11);
                float2 f0 = unpackh2(h0);
                float2 f1 = unpackh2(h1);
                *(uint32_t*)&Ch[(size_t)row0 * N + col] = h0;
                *(uint32_t*)&Ch[(size_t)(row0 + 8) * N + col] = h1;
                *(uint32_t*)&Cl[(size_t)row0 * N + col] = packh2(v00 - f0.x, v01 - f0.y);
                *(uint32_t*)&Cl[(size_t)(row0 + 8) * N + col] = packh2(v10 - f1.x, v11 - f1.y);
            }
        }
    }
}

// ---------------------------------------------------------------------------
// Tensor-core causal flash attention (fp16).
// QK: 3 products fp16 (err ~2^-22). PV: P single fp16 x V hi/lo (2 products).
// CTA: 128 q-rows x d=64, 8 warps x 16 rows. 64-key tiles, 3-stage pipeline.
// Output ctx written as bf16 hi/lo (feeds bf16 out-proj GEMM).
// ---------------------------------------------------------------------------
#define AQ 128
#define AKT 64
#define STG_A 32768                      // Kh,Kl,Vh,Vl @ 8KB each
#define ATT_SMEM (3 * STG_A)             // 98304 bytes -> 2 CTAs/SM

__global__ __launch_bounds__(256)
void attn_mma() {
    extern __shared__ __half smh[];
    const int tid = threadIdx.x, lane = tid & 31, wid = tid >> 5;
    const int bh = blockIdx.y, b = bh >> 4, h = bh & 15;
    const int qt = gridDim.x - 1 - blockIdx.x;   // heavy tiles first
    const int q0 = qt * AQ;
    const uint32_t sbase = smem_u32(smh);
    const size_t rowb = (size_t)b * Mq;

    const uint32_t QhB = sbase + 2 * STG_A;      // Q parks in stage 2
    const uint32_t QlB = QhB + 16384;

    // ---- load Q tile (hi/lo) into stage-2 region ----
    #pragma unroll
    for (int l = tid; l < 2048; l += 256) {
        int arr = l >> 10;                        // 0:h 1:l
        int r = (l >> 3) & 127;
        int c = l & 7;
        const __half* g = (arr ? g_qkvl : g_qkvh) +
            (rowb + q0 + r) * N3 + h * 64 + c * 8;
        cp16((arr ? QlB : QhB) + swz8(r, c), g);
    }
    cp_commit();

    auto load_kv = [&](int stg_i, int j0) {
        uint32_t base = sbase + (uint32_t)(stg_i * STG_A);
        #pragma unroll
        for (int l = tid; l < 2048; l += 256) {
            int arr = l >> 9;                     // 0:Kh 1:Kl 2:Vh 3:Vl
            int r = (l >> 3) & 63;
            int c = l & 7;
            size_t roff = (rowb + j0 + r) * N3 + h * 64 + c * 8;
            const __half* g =
                (arr == 0) ? g_qkvh + roff + Nq :
                (arr == 1) ? g_qkvl + roff + Nq :
                (arr == 2) ? g_qkvh + roff + 2 * Nq :
                             g_qkvl + roff + 2 * Nq;
            cp16(base + (uint32_t)(arr * 8192) + swz8(r, c), g);
        }
        cp_commit();
    };

    const int nkt = (q0 + AQ) / AKT;             // >= 2 always
    load_kv(0, 0);
    load_kv(1, AKT);

    // ---- Q fragments into registers (once); stage 2 is then free for KV ----
    cp_wait<2>();                                // retires the Q group
    __syncthreads();                             // publish all threads' Q copies
    uint32_t qhf[4][4], qlf[4][4];
    {
        int r = wid * 16 + (lane & 15);
        int chq = lane >> 4;
        #pragma unroll
        for (int ks = 0; ks < 4; ks++) {
            ldm4(qhf[ks], QhB + swz8(r, 2 * ks + chq));
            ldm4(qlf[ks], QlB + swz8(r, 2 * ks + chq));
        }
    }

    float m0 = -1e30f, m1 = -1e30f, l0 = 0.0f, l1 = 0.0f;
    float O[8][4];
    #pragma unroll
    for (int f = 0; f < 8; f++)
        #pragma unroll
        for (int c = 0; c < 4; c++) O[f][c] = 0.0f;

    const float scale = 0.125f;
    const int rbase0 = q0 + wid * 16 + (lane >> 2);
    const int kR = (lane & 7) + ((lane >> 4) << 3);
    const int chK = (lane >> 3) & 1;
    const int vR = lane & 15;
    const int chV = lane >> 4;

    for (int kt = 0; kt < nkt; kt++) {
        const int j0 = kt * AKT;
        if (kt + 1 < nkt) cp_wait<1>();
        else              cp_wait<0>();
        __syncthreads();                          // single barrier per tile
        if (kt + 2 < nkt) load_kv((kt + 2) % 3, (kt + 2) * AKT);

        const uint32_t stg = sbase + (uint32_t)((kt % 3) * STG_A);
        const uint32_t sKh = stg;
        const uint32_t sVh = stg + 16384;

        // ---- scores = Q K^T (3 split products) ----
        float s[8][4];
        #pragma unroll
        for (int f = 0; f < 8; f++)
            #pragma unroll
            for (int c = 0; c < 4; c++) s[f][c] = 0.0f;

        #pragma unroll
        for (int ks = 0; ks < 4; ks++) {
            #pragma unroll
            for (int p = 0; p < 4; p++) {
                uint32_t addr = sKh + swz8(p * 16 + kR, 2 * ks + chK);
                uint32_t kh4[4], kl4[4];
                ldm4(kh4, addr);
                ldm4(kl4, addr + 8192);
                mma16816h(s[2 * p],     qhf[ks], kh4[0], kh4[1]);
                mma16816h(s[2 * p + 1], qhf[ks], kh4[2], kh4[3]);
                mma16816h(s[2 * p],     qhf[ks], kl4[0], kl4[1]);
                mma16816h(s[2 * p + 1], qhf[ks], kl4[2], kl4[3]);
                mma16816h(s[2 * p],     qlf[ks], kh4[0], kh4[1]);
                mma16816h(s[2 * p + 1], qlf[ks], kh4[2], kh4[3]);
            }
        }

        // ---- scale + causal mask (diagonal tiles only) ----
        if (j0 + AKT - 1 > q0) {
            #pragma unroll
            for (int f = 0; f < 8; f++) {
                int k0c = j0 + f * 8 + (lane & 3) * 2;
                #pragma unroll
                for (int c = 0; c < 4; c++) {
                    int key = k0c + (c & 1);
                    int row = rbase0 + ((c >> 1) * 8);
                    s[f][c] = (key > row) ? -1e30f : s[f][c] * scale;
                }
            }
        } else {
            #pragma unroll
            for (int f = 0; f < 8; f++)
                #pragma unroll
                for (int c = 0; c < 4; c++) s[f][c] *= scale;
        }

        // ---- online softmax ----
        float bm0 = -1e30f, bm1 = -1e30f;
        #pragma unroll
        for (int f = 0; f < 8; f++) {
            bm0 = fmaxf(bm0, fmaxf(s[f][0], s[f][1]));
            bm1 = fmaxf(bm1, fmaxf(s[f][2], s[f][3]));
        }
        bm0 = fmaxf(bm0, __shfl_xor_sync(0xffffffff, bm0, 1));
        bm0 = fmaxf(bm0, __shfl_xor_sync(0xffffffff, bm0, 2));
        bm1 = fmaxf(bm1, __shfl_xor_sync(0xffffffff, bm1, 1));
        bm1 = fmaxf(bm1, __shfl_xor_sync(0xffffffff, bm1, 2));
        float mn0 = fmaxf(m0, bm0), mn1 = fmaxf(m1, bm1);
        float corr0 = fexp(m0 - mn0), corr1 = fexp(m1 - mn1);
        m0 = mn0; m1 = mn1;

        float es0 = 0.0f, es1 = 0.0f;
        #pragma unroll
        for (int f = 0; f < 8; f++) {
            s[f][0] = fexp(s[f][0] - m0);
            s[f][1] = fexp(s[f][1] - m0);
            s[f][2] = fexp(s[f][2] - m1);
            s[f][3] = fexp(s[f][3] - m1);
            es0 += s[f][0] + s[f][1];
            es1 += s[f][2] + s[f][3];
        }
        es0 += __shfl_xor_sync(0xffffffff, es0, 1);
        es0 += __shfl_xor_sync(0xffffffff, es0, 2);
        es1 += __shfl_xor_sync(0xffffffff, es1, 1);
        es1 += __shfl_xor_sync(0xffffffff, es1, 2);
        l0 = l0 * corr0 + es0;
        l1 = l1 * corr1 + es1;

        #pragma unroll
        for (int f = 0; f < 8; f++) {
            O[f][0] *= corr0; O[f][1] *= corr0;
            O[f][2] *= corr1; O[f][3] *= corr1;
        }

        // ---- P @ V (P single fp16, V hi/lo: 2 products) ----
        #pragma unroll
        for (int ks2 = 0; ks2 < 4; ks2++) {
            uint32_t aH[4];
            #pragma unroll
            for (int q = 0; q < 2; q++) {
                aH[2 * q + 0] = packh2(s[2 * ks2 + q][0], s[2 * ks2 + q][1]);
                aH[2 * q + 1] = packh2(s[2 * ks2 + q][2], s[2 * ks2 + q][3]);
            }
            #pragma unroll
            for (int p2i = 0; p2i < 4; p2i++) {
                uint32_t addr = sVh + swz8(ks2 * 16 + vR, 2 * p2i + chV);
                uint32_t vh4[4], vl4[4];
                ldm4t(vh4, addr);
                ldm4t(vl4, addr + 8192);
                mma16816h(O[2 * p2i],     aH, vh4[0], vh4[1]);
                mma16816h(O[2 * p2i + 1], aH, vh4[2], vh4[3]);
                mma16816h(O[2 * p2i],     aH, vl4[0], vl4[1]);
                mma16816h(O[2 * p2i + 1], aH, vl4[2], vl4[3]);
            }
        }
    }

    // ---- epilogue: normalize, write ctx bf16 hi/lo ----
    float inv0 = 1.0f / l0, inv1 = 1.0f / l1;
    size_t base0 = (rowb + rbase0) * Nq + h * 64;
    size_t base1 = (rowb + rbase0 + 8) * Nq + h * 64;
    #pragma unroll
    for (int f = 0; f < 8; f++) {
        int col = f * 8 + (lane & 3) * 2;
        float v00 = O[f][0] * inv0, v01 = O[f][1] * inv0;
        float v10 = O[f][2] * inv1, v11 = O[f][3] * inv1;
        uint32_t h0 = cvt2(v01, v00);
        uint32_t h1 = cvt2(v11, v10);
        float r00 = v00 - __int_as_float(h0 << 16);
        float r01 = v01 - __int_as_float(h0 & 0xffff0000u);
        float r10 = v10 - __int_as_float(h1 << 16);
        float r11 = v11 - __int_as_float(h1 & 0xffff0000u);
        *(uint32_t*)&g_ch[base0 + col] = h0;
        *(uint32_t*)&g_cl[base0 + col] = cvt2(r01, r00);
        *(uint32_t*)&g_ch[base1 + col] = h1;
        *(uint32_t*)&g_cl[base1 + col] = cvt2(r11, r10);
    }
}

// ---------------------------------------------------------------------------
extern "C" void kernel_launch(void* const* d_in, const int* in_sizes, int n_in,
                              void* d_out, int out_size) {
    const float* x      = (const float*)d_in[0];
    const float* w_attn = (const float*)d_in[1];
    const float* w_proj = (const float*)d_in[2];
    const float* b_attn = (const float*)d_in[3];
    const float* b_proj = (const float*)d_in[4];
    float* out = (float*)d_out;

    __half *qh, *ql;
    __nv_bfloat16 *xh, *xl, *wah, *wal, *wph, *wpl, *ch, *cl;
    cudaGetSymbolAddress((void**)&qh, g_qkvh);
    cudaGetSymbolAddress((void**)&ql, g_qkvl);
    cudaGetSymbolAddress((void**)&xh, g_xh);
    cudaGetSymbolAddress((void**)&xl, g_xl);
    cudaGetSymbolAddress((void**)&wah, g_wah);
    cudaGetSymbolAddress((void**)&wal, g_wal);
    cudaGetSymbolAddress((void**)&wph, g_wph);
    cudaGetSymbolAddress((void**)&wpl, g_wpl);
    cudaGetSymbolAddress((void**)&ch, g_ch);
    cudaGetSymbolAddress((void**)&cl, g_cl);

    static bool attr_set = false;
    if (!attr_set) {
        cudaFuncSetAttribute(gemm_mma, cudaFuncAttributeMaxDynamicSharedMemorySize,
                             GEMM_SMEM);
        cudaFuncSetAttribute(attn_mma, cudaFuncAttributeMaxDynamicSharedMemorySize,
                             ATT_SMEM);
        attr_set = true;
    }

    // conversions (bf16 splits for the GEMM inputs)
    {
        int n = MB * Nq;
        split_kernel<<<(n + 255) / 256, 256>>>(x, xh, xl, n);
    }
    splitT_kernel<<<dim3(N3 / 32, Nq / 32), dim3(32, 8)>>>(w_attn, wah, wal, Nq, N3);
    splitT_kernel<<<dim3(Nq / 32, Nq / 32), dim3(32, 8)>>>(w_proj, wph, wpl, Nq, Nq);

    // QKV projection (bf16 math) -> fp16 hi/lo qkv
    gemm_mma<<<dim3(N3 / 128, MB / 128), 128, GEMM_SMEM>>>(
        xh, xl, wah, wal, b_attn, nullptr, qh, ql, N3);

    // causal flash attention (fp16) -> ctx bf16 hi/lo
    attn_mma<<<dim3(Mq / AQ, Bq * Hh), 256, ATT_SMEM>>>();

    // output projection (bf16 math) -> fp32 out
    gemm_mma<<<dim3(Nq / 128, MB / 128), 128, GEMM_SMEM>>>(
        ch, cl, wph, wpl, b_proj, out, nullptr, nullptr, Nq);
}